// round 9
// baseline (speedup 1.0000x reference)
#include <cuda_runtime.h>
#include <cuda_fp16.h>
#include <cstdint>

#define BATCH 4
#define SEQ   2048
#define EDIM  1024
#define QN    4
#define HN    16
#define DH    64
#define NTOK  (BATCH*SEQ)        // 8192
#define QCOLS (QN*EDIM)          // 4096
#define NQKV  (QCOLS + 2*EDIM)   // 6144

// ------------------------- scratch (static, no runtime alloc) ---------------
__device__ __half g_qkv[(size_t)NTOK * NQKV];    // fused q|k|v projections
__device__ __half g_xf[(size_t)NTOK * EDIM];     // x fp16
__device__ __half g_y[(size_t)NTOK * EDIM];      // attn out (B,H,S,D) flat
__device__ __half g_wqkv[(size_t)NQKV * EDIM];   // packed Wq|Wk|Wv fp16
__device__ __half g_wo[(size_t)EDIM * EDIM];

// ------------------------- helpers ------------------------------------------
__device__ __forceinline__ uint32_t smem_to_u32(const void* p) {
    uint32_t a;
    asm("{ .reg .u64 t; cvta.to.shared.u64 t, %1; cvt.u32.u64 %0, t; }" : "=r"(a) : "l"(p));
    return a;
}
__device__ __forceinline__ void cp16(uint32_t dst, const void* src) {
    asm volatile("cp.async.cg.shared.global [%0], [%1], 16;" :: "r"(dst), "l"(src));
}
__device__ __forceinline__ void cp_commit() { asm volatile("cp.async.commit_group;" ::: "memory"); }
__device__ __forceinline__ void cp_wait0()  { asm volatile("cp.async.wait_group 0;"  ::: "memory"); }
__device__ __forceinline__ void cp_wait1()  { asm volatile("cp.async.wait_group 1;"  ::: "memory"); }
__device__ __forceinline__ void ldx4(uint32_t* r, uint32_t addr) {
    asm volatile("ldmatrix.sync.aligned.m8n8.x4.shared.b16 {%0,%1,%2,%3}, [%4];"
        : "=r"(r[0]), "=r"(r[1]), "=r"(r[2]), "=r"(r[3]) : "r"(addr));
}
__device__ __forceinline__ void mma16816(float* d, const uint32_t* a, const uint32_t* b) {
    asm volatile("mma.sync.aligned.m16n8k16.row.col.f32.f16.f16.f32 "
        "{%0,%1,%2,%3}, {%4,%5,%6,%7}, {%8,%9}, {%0,%1,%2,%3};"
        : "+f"(d[0]), "+f"(d[1]), "+f"(d[2]), "+f"(d[3])
        : "r"(a[0]), "r"(a[1]), "r"(a[2]), "r"(a[3]), "r"(b[0]), "r"(b[1]));
}

// ------------------------- fused conversion ---------------------------------
#define S_X   2097152
#define S_WQ  (S_X  + 1048576)
#define S_WK  (S_WQ + 262144)
#define S_WV  (S_WK + 262144)
#define S_ALL (S_WV + 262144)

__device__ __forceinline__ uint2 f4_to_h4(float4 v) {
    __half2 h[2];
    h[0] = __floats2half2_rn(v.x, v.y);
    h[1] = __floats2half2_rn(v.z, v.w);
    return *(uint2*)h;
}

__global__ void __launch_bounds__(256)
conv_all(const float* __restrict__ x, const float* __restrict__ Wq,
         const float* __restrict__ Wk, const float* __restrict__ Wv,
         const float* __restrict__ Wo, __half* __restrict__ xf,
         __half* __restrict__ wqkv, __half* __restrict__ wo)
{
    int i = blockIdx.x * 256 + threadIdx.x;
    if (i >= S_ALL) return;
    const float4* src; uint2* dst; int j;
    if (i < S_X)       { src = (const float4*)x;  dst = (uint2*)xf;   j = i; }
    else if (i < S_WQ) { src = (const float4*)Wq; dst = (uint2*)wqkv; j = i - S_X; }
    else if (i < S_WK) { src = (const float4*)Wk; dst = (uint2*)wqkv + 1048576; j = i - S_WQ; }
    else if (i < S_WV) { src = (const float4*)Wv; dst = (uint2*)wqkv + 1310720; j = i - S_WK; }
    else               { src = (const float4*)Wo; dst = (uint2*)wo;   j = i - S_WV; }
    dst[j] = f4_to_h4(src[j]);
}

// ------------------------- persistent HMMA fp16 GEMM ------------------------
// C[m,n] = sum_k A[m,k]*W[n,k] + bias[n].  128x128 tiles, BK=64, 4 warps
// (warp tile 64x64), 3-stage cp.async pipeline running CONTINUOUSLY across
// the CTA's whole tile list (persistent CTAs, 2/SM). K is fixed at 1024
// (16 chunks/tile). XOR-swizzled 128B rows.
#define GBK    64
#define TILEB  (128 * 128)
#define STAGEB (2 * TILEB)
#define NSTG   3
#define GSMEM  (NSTG * STAGEB)      // 98304 B
#define NCHUNK 16                   // K=1024 / 64

template <typename OutT>
__global__ void __launch_bounds__(128, 2)
gemm_f16(const __half* __restrict__ A, const __half* __restrict__ W,
         const float* __restrict__ bias0, const float* __restrict__ bias1,
         const float* __restrict__ bias2, int nb1, int nb2,
         OutT* __restrict__ C, int M, int N)
{
    extern __shared__ __align__(16) char smem[];
    const uint32_t sb = smem_to_u32(smem);
    const int tid = threadIdx.x;
    const int lane = tid & 31;
    const int warp = tid >> 5;
    const int wm0 = (warp & 1) * 64;
    const int wn0 = (warp >> 1) * 64;
    const int K = EDIM;

    const int nt_n = N >> 7;
    const int ntiles = (M >> 7) * nt_n;
    const int mytiles = (ntiles - (int)blockIdx.x + (int)gridDim.x - 1) / (int)gridDim.x;
    if (mytiles <= 0) return;
    const int totc = mytiles * NCHUNK;

    const int lrow = tid >> 3;
    const int lq   = tid & 7;

    auto load_chunk_g = [&](int ci) {
        const int ti = ci >> 4;
        const int c  = ci & 15;
        const int t  = (int)blockIdx.x + ti * (int)gridDim.x;
        const int bm = (t / nt_n) << 7;
        const int bn = (t % nt_n) << 7;
        const uint32_t stb = sb + (ci % NSTG) * STAGEB;
#pragma unroll
        for (int l = 0; l < 8; l++) {
            int row = lrow + l * 16;
            uint32_t dst = stb + row * 128 + ((lq ^ (row & 7)) << 4);
            const size_t kof = (size_t)c * GBK + lq * 8;
            cp16(dst,         A + (size_t)(bm + row) * K + kof);
            cp16(dst + TILEB, W + (size_t)(bn + row) * K + kof);
        }
    };

    const int arow[4] = {wm0 + 0 * 16 + (lane & 15), wm0 + 1 * 16 + (lane & 15),
                         wm0 + 2 * 16 + (lane & 15), wm0 + 3 * 16 + (lane & 15)};
    const int ahalf = lane >> 4;
    const int brow[4] = {wn0 + 0 * 16 + (lane & 7) + ((lane >> 4) << 3),
                         wn0 + 1 * 16 + (lane & 7) + ((lane >> 4) << 3),
                         wn0 + 2 * 16 + (lane & 7) + ((lane >> 4) << 3),
                         wn0 + 3 * 16 + (lane & 7) + ((lane >> 4) << 3)};
    const int bhalf = (lane >> 3) & 1;

    float acc[4][8][4];
#pragma unroll
    for (int i = 0; i < 4; i++)
#pragma unroll
        for (int j = 0; j < 8; j++)
#pragma unroll
            for (int r = 0; r < 4; r++) acc[i][j][r] = 0.f;

    load_chunk_g(0); cp_commit();
    if (totc > 1) { load_chunk_g(1); cp_commit(); }

    for (int ci = 0; ci < totc; ci++) {
        if (ci + 1 < totc) cp_wait1(); else cp_wait0();
        __syncthreads();
        if (ci + 2 < totc) { load_chunk_g(ci + 2); cp_commit(); }

        {   // compute on stage ci % NSTG
            const uint32_t tA = sb + (ci % NSTG) * STAGEB;
            const uint32_t tW = tA + TILEB;
#pragma unroll
            for (int ks = 0; ks < 4; ks++) {
                uint32_t a[4][4], b[4][4];
#pragma unroll
                for (int rb = 0; rb < 4; rb++) {
                    int r = arow[rb];
                    uint32_t q = (uint32_t)((2 * ks + ahalf) ^ (r & 7));
                    ldx4(a[rb], tA + (uint32_t)r * 128 + (q << 4));
                }
#pragma unroll
                for (int hb = 0; hb < 4; hb++) {
                    int r = brow[hb];
                    uint32_t q = (uint32_t)((2 * ks + bhalf) ^ (r & 7));
                    ldx4(b[hb], tW + (uint32_t)r * 128 + (q << 4));
                }
#pragma unroll
                for (int rb = 0; rb < 4; rb++) {
#pragma unroll
                    for (int nb = 0; nb < 8; nb++) {
                        mma16816(acc[rb][nb], a[rb], &b[nb >> 1][(nb & 1) * 2]);
                    }
                }
            }
        }

        if ((ci & 15) == 15) {
            // tile finished: epilogue (overlaps with next tile's in-flight loads)
            const int ti = ci >> 4;
            const int t  = (int)blockIdx.x + ti * (int)gridDim.x;
            const int bm = (t / nt_n) << 7;
            const int bn = (t % nt_n) << 7;
            const float* bp; int segbase;
            if (bn < nb1)      { bp = bias0; segbase = 0;   }
            else if (bn < nb2) { bp = bias1; segbase = nb1; }
            else               { bp = bias2; segbase = nb2; }
#pragma unroll
            for (int rb = 0; rb < 4; rb++) {
#pragma unroll
                for (int nb = 0; nb < 8; nb++) {
                    int row = bm + wm0 + rb * 16 + (lane >> 2);
                    int col = bn + wn0 + nb * 8 + (lane & 3) * 2;
                    float b0 = bp[col - segbase], b1 = bp[col - segbase + 1];
                    float o0 = acc[rb][nb][0] + b0, o1 = acc[rb][nb][1] + b1;
                    float o2 = acc[rb][nb][2] + b0, o3 = acc[rb][nb][3] + b1;
                    if constexpr (sizeof(OutT) == 2) {
                        __half2 h0 = __floats2half2_rn(o0, o1);
                        __half2 h1 = __floats2half2_rn(o2, o3);
                        *(__half2*)((__half*)C + (size_t)row * N + col)       = h0;
                        *(__half2*)((__half*)C + (size_t)(row + 8) * N + col) = h1;
                    } else {
                        float2 v0 = {o0, o1}, v1 = {o2, o3};
                        *(float2*)((float*)C + (size_t)row * N + col)       = v0;
                        *(float2*)((float*)C + (size_t)(row + 8) * N + col) = v1;
                    }
                    acc[rb][nb][0] = 0.f; acc[rb][nb][1] = 0.f;
                    acc[rb][nb][2] = 0.f; acc[rb][nb][3] = 0.f;
                }
            }
        }
    }
}

// ------------------------- per-token head-mixing attention ------------------
#define KSTR 68
__global__ void __launch_bounds__(256)
attn_kernel(const __half* __restrict__ gqkv, __half* __restrict__ gy)
{
    const int tok = blockIdx.x;
    const int t = threadIdx.x;
    const __half* base = gqkv + (size_t)tok * NQKV;

    __shared__ __align__(16) float qs[QN * HN * DH];
    __shared__ __align__(16) float ks[HN * KSTR];
    __shared__ __align__(16) float vs[HN * DH];
    __shared__ float sc[QN][HN][HN];
    __shared__ float ps[HN][HN];

    {
        const uint4* qg = (const uint4*)base;
#pragma unroll
        for (int l = 0; l < 2; l++) {
            uint4 p = qg[t + l * 256];
            const __half2* hp = (const __half2*)&p;
            float* dst = qs + (t + l * 256) * 8;
#pragma unroll
            for (int j = 0; j < 4; j++) {
                float2 f = __half22float2(hp[j]);
                dst[2 * j] = f.x; dst[2 * j + 1] = f.y;
            }
        }
    }
    if (t < 128) {
        uint4 p = ((const uint4*)(base + QCOLS))[t];
        const __half2* hp = (const __half2*)&p;
        int g = t >> 3, d = (t * 8) & 63;
        float* kr = ks + g * KSTR + d;
#pragma unroll
        for (int j = 0; j < 4; j++) {
            float2 f = __half22float2(hp[j]);
            kr[2 * j] = f.x; kr[2 * j + 1] = f.y;
        }
    } else {
        int tt = t - 128;
        uint4 p = ((const uint4*)(base + QCOLS + EDIM))[tt];
        const __half2* hp = (const __half2*)&p;
        int g = tt >> 3, d = (tt * 8) & 63;
        float* vr = vs + g * DH + d;
#pragma unroll
        for (int j = 0; j < 4; j++) {
            float2 f = __half22float2(hp[j]);
            vr[2 * j] = f.x; vr[2 * j + 1] = f.y;
        }
    }
    __syncthreads();

    const float scale = 0.125f;
#pragma unroll
    for (int l = 0; l < 4; l++) {
        int e = t + l * 256;
        int qq = e >> 8, h = (e >> 4) & 15, g = e & 15;
        const float4* qp4 = (const float4*)(qs + (qq * HN + h) * DH);
        const float4* kp4 = (const float4*)(ks + g * KSTR);
        float s_ = 0.f;
#pragma unroll
        for (int d = 0; d < 16; d++) {
            float4 a = qp4[d], b = kp4[d];
            s_ += a.x * b.x + a.y * b.y + a.z * b.z + a.w * b.w;
        }
        sc[qq][h][g] = s_ * scale;
    }
    __syncthreads();

    if (t < 64) {
        int qq = t >> 4, h = t & 15;
        float* row = sc[qq][h];
        float m = row[0];
#pragma unroll
        for (int g = 1; g < 16; g++) m = fmaxf(m, row[g]);
        float ssum = 0.f;
#pragma unroll
        for (int g = 0; g < 16; g++) { float ex = __expf(row[g] - m); row[g] = ex; ssum += ex; }
        float inv = 1.f / ssum;
#pragma unroll
        for (int g = 0; g < 16; g++) row[g] *= inv;
    }
    __syncthreads();

    {
        int h = t >> 4, g = t & 15;
        ps[h][g] = sc[0][h][g] + sc[1][h][g] + sc[2][h][g] + sc[3][h][g];
    }
    __syncthreads();

    const int b = tok >> 11, s = tok & 2047;
    {
        int h = t >> 4;
        int d0 = (t * 4) & 63;
        const float4* vp4 = (const float4*)vs;
        float4 o = {0.f, 0.f, 0.f, 0.f};
#pragma unroll
        for (int g = 0; g < 16; g++) {
            float p = ps[h][g];
            float4 vv = vp4[g * 16 + (d0 >> 2)];
            o.x = fmaf(p, vv.x, o.x); o.y = fmaf(p, vv.y, o.y);
            o.z = fmaf(p, vv.z, o.z); o.w = fmaf(p, vv.w, o.w);
        }
        __half2 h0 = __floats2half2_rn(o.x, o.y);
        __half2 h1 = __floats2half2_rn(o.z, o.w);
        size_t oi = (((size_t)b * HN + h) * SEQ + s) * DH + d0;
        *(__half2*)(gy + oi)     = h0;
        *(__half2*)(gy + oi + 2) = h1;
    }
}

// ------------------------- launch -------------------------------------------
extern "C" void kernel_launch(void* const* d_in, const int* in_sizes, int n_in,
                              void* d_out, int out_size)
{
    const float* x  = (const float*)d_in[0];
    const float* Wq = (const float*)d_in[1];
    const float* bq = (const float*)d_in[2];
    const float* Wk = (const float*)d_in[3];
    const float* bk = (const float*)d_in[4];
    const float* Wv = (const float*)d_in[5];
    const float* bv = (const float*)d_in[6];
    const float* Wo = (const float*)d_in[7];
    const float* bo = (const float*)d_in[8];
    float* out = (float*)d_out;
    (void)in_sizes; (void)n_in; (void)out_size;

    __half *qkv, *xf, *gy, *wqkv, *wo;
    cudaGetSymbolAddress((void**)&qkv, g_qkv);
    cudaGetSymbolAddress((void**)&xf, g_xf);
    cudaGetSymbolAddress((void**)&gy, g_y);
    cudaGetSymbolAddress((void**)&wqkv, g_wqkv);
    cudaGetSymbolAddress((void**)&wo, g_wo);

    cudaFuncSetAttribute(gemm_f16<float>,  cudaFuncAttributeMaxDynamicSharedMemorySize, GSMEM);
    cudaFuncSetAttribute(gemm_f16<__half>, cudaFuncAttributeMaxDynamicSharedMemorySize, GSMEM);

    const int PERSIST = 2 * 148;   // 2 CTAs per SM

    // 1) fused fp32 -> fp16 conversions
    conv_all<<<(S_ALL + 255) / 256, 256>>>(x, Wq, Wk, Wv, Wo, xf, wqkv, wo);

    // 2) fused QKV projection (persistent, N = 6144)
    {
        int ntiles = (NTOK / 128) * (NQKV / 128);      // 3072
        int grid = ntiles < PERSIST ? ntiles : PERSIST;
        gemm_f16<__half><<<grid, 128, GSMEM>>>(
            xf, wqkv, bq, bk, bv, QCOLS, QCOLS + EDIM, qkv, NTOK, NQKV);
    }

    // 3) per-token attention -> y fp16 ((B,H,S,D) flat == (B,S,E) flat)
    attn_kernel<<<NTOK, 256>>>(qkv, gy);

    // 4) output projection (persistent, fp32 out)
    {
        int ntiles = (NTOK / 128) * (EDIM / 128);      // 512
        int grid = ntiles < PERSIST ? ntiles : PERSIST;
        gemm_f16<float><<<grid, 128, GSMEM>>>(
            gy, wo, bo, bo, bo, 1 << 30, 1 << 30, out, NTOK, EDIM);
    }
}